// round 15
// baseline (speedup 1.0000x reference)
#include <cuda_runtime.h>
#include <cuda_bf16.h>
#include <math.h>
#include <stdint.h>

// ---------------- problem constants ----------------
#define BATCH 2
#define C_IN 192
#define C3 576
#define HW 65536
#define IMG 256
#define HEADS 6
#define CH 32
#define WS 8
#define NTOK 64
#define NWIN 2048
#define NPAIR 32

__device__ float g_qkv1[(size_t)BATCH * C3 * HW];
// K3-ready buffers written by K2:
//   g_q/g_k : l2-normalized bf16 token-pairs [win][head][c][pair]
//   g_vh/g_vl : v split hi/lo bf16 token-pairs
__device__ uint32_t g_q [(size_t)NWIN * HEADS * CH * NPAIR];
__device__ uint32_t g_k [(size_t)NWIN * HEADS * CH * NPAIR];
__device__ uint32_t g_vh[(size_t)NWIN * HEADS * CH * NPAIR];
__device__ uint32_t g_vl[(size_t)NWIN * HEADS * CH * NPAIR];
__device__ float g_att[(size_t)BATCH * C_IN * HW];

// ---------------------------------------------------------------------------
// bf16 helpers (pair-packed b32: low 16 = even element, high 16 = odd)
// ---------------------------------------------------------------------------
__device__ __forceinline__ void split2(float e0, float e1, uint32_t& hp, uint32_t& lp)
{
    __nv_bfloat16 h0 = __float2bfloat16(e0);
    __nv_bfloat16 h1 = __float2bfloat16(e1);
    __nv_bfloat16 l0 = __float2bfloat16(e0 - __bfloat162float(h0));
    __nv_bfloat16 l1 = __float2bfloat16(e1 - __bfloat162float(h1));
    __nv_bfloat162 hh; hh.x = h0; hh.y = h1;
    __nv_bfloat162 ll; ll.x = l0; ll.y = l1;
    hp = *reinterpret_cast<uint32_t*>(&hh);
    lp = *reinterpret_cast<uint32_t*>(&ll);
}

__device__ __forceinline__ uint32_t pack_hi(float e0, float e1)
{
    __nv_bfloat162 hh; hh.x = __float2bfloat16(e0); hh.y = __float2bfloat16(e1);
    return *reinterpret_cast<uint32_t*>(&hh);
}

__device__ __forceinline__ void mma16816(float* d, const uint32_t* a, uint32_t b0, uint32_t b1)
{
    asm volatile(
        "mma.sync.aligned.m16n8k16.row.col.f32.bf16.bf16.f32 "
        "{%0,%1,%2,%3}, {%4,%5,%6,%7}, {%8,%9}, {%0,%1,%2,%3};"
        : "+f"(d[0]), "+f"(d[1]), "+f"(d[2]), "+f"(d[3])
        : "r"(a[0]), "r"(a[1]), "r"(a[2]), "r"(a[3]), "r"(b0), "r"(b1));
}

// ---------------------------------------------------------------------------
// K1/K4: GEMM (R10, proven). CTA 64x256x32, 8 warps 2x4, warp tile 32x64,
// conflict-free X pack, launch_bounds(256,2).
// ---------------------------------------------------------------------------
__global__ __launch_bounds__(256, 2) void k_gemm_mma(
    const float* __restrict__ Wt, const float* __restrict__ Xall,
    float* __restrict__ Yall, const float* __restrict__ bias, int M)
{
    const float* X = Xall + (size_t)blockIdx.z * C_IN * HW;
    float* Y = Yall + (size_t)blockIdx.z * (size_t)M * HW;
    const int oTile = blockIdx.y * 64;
    const int pTile = blockIdx.x * 256;

    __shared__ uint32_t WsH[2][64][9], WsL[2][64][9];
    __shared__ uint32_t XsH[2][256][9], XsL[2][256][9];

    const int tid = threadIdx.x;
    const int lane = tid & 31;
    const int wid = tid >> 5;
    const int warpM = wid >> 2;
    const int warpN = wid & 3;
    const int g = lane >> 2;
    const int t = lane & 3;

    float acc[2][8][4];
#pragma unroll
    for (int im = 0; im < 2; im++)
#pragma unroll
        for (int jn = 0; jn < 8; jn++)
#pragma unroll
            for (int r = 0; r < 4; r++) acc[im][jn][r] = 0.f;

    const int wo = tid >> 2;
    const int wsub = tid & 3;

    for (int k0 = 0; k0 < 192; k0 += 32) {
        {
            const float* wptr = &Wt[(size_t)(oTile + wo) * 192 + k0 + wsub * 8];
            float4 f0 = *(const float4*)wptr;
            float4 f1 = *(const float4*)(wptr + 4);
            float f[8] = {f0.x, f0.y, f0.z, f0.w, f1.x, f1.y, f1.z, f1.w};
#pragma unroll
            for (int j = 0; j < 4; j++) {
                uint32_t hp, lp;
                split2(f[2 * j], f[2 * j + 1], hp, lp);
                int kk2 = wsub * 4 + j;
                int ch = kk2 >> 3, cc = kk2 & 7;
                WsH[ch][wo][cc] = hp;
                WsL[ch][wo][cc] = lp;
            }
        }
        {
#pragma unroll
            for (int it = 0; it < 2; it++) {
                int kp = (tid >> 5) + it * 8;
                int ch = kp >> 3, cc = kp & 7;
                const float* r0 = X + (size_t)(k0 + 2 * kp) * HW + pTile + lane;
#pragma unroll
                for (int pm = 0; pm < 8; pm++) {
                    float f0 = r0[pm * 32];
                    float f1 = r0[pm * 32 + HW];
                    uint32_t hp, lp;
                    split2(f0, f1, hp, lp);
                    XsH[ch][lane + 32 * pm][cc] = hp;
                    XsL[ch][lane + 32 * pm][cc] = lp;
                }
            }
        }
        __syncthreads();

#pragma unroll
        for (int ch = 0; ch < 2; ch++) {
            uint32_t Ah[2][4], Al[2][4];
#pragma unroll
            for (int im = 0; im < 2; im++) {
                int r0 = warpM * 32 + im * 16 + g;
                Ah[im][0] = WsH[ch][r0][t];
                Ah[im][1] = WsH[ch][r0 + 8][t];
                Ah[im][2] = WsH[ch][r0][t + 4];
                Ah[im][3] = WsH[ch][r0 + 8][t + 4];
                Al[im][0] = WsL[ch][r0][t];
                Al[im][1] = WsL[ch][r0 + 8][t];
                Al[im][2] = WsL[ch][r0][t + 4];
                Al[im][3] = WsL[ch][r0 + 8][t + 4];
            }
#pragma unroll
            for (int jn = 0; jn < 8; jn++) {
                int col = warpN * 64 + jn * 8 + g;
                uint32_t bh0 = XsH[ch][col][t], bh1 = XsH[ch][col][t + 4];
                uint32_t bl0 = XsL[ch][col][t], bl1 = XsL[ch][col][t + 4];
#pragma unroll
                for (int im = 0; im < 2; im++) {
                    mma16816(acc[im][jn], Al[im], bh0, bh1);
                    mma16816(acc[im][jn], Ah[im], bl0, bl1);
                    mma16816(acc[im][jn], Ah[im], bh0, bh1);
                }
            }
        }
        __syncthreads();
    }

#pragma unroll
    for (int im = 0; im < 2; im++) {
        int row = oTile + warpM * 32 + im * 16 + g;
        float bs0 = bias ? bias[row] : 0.f;
        float bs1 = bias ? bias[row + 8] : 0.f;
#pragma unroll
        for (int jn = 0; jn < 8; jn++) {
            int col = pTile + warpN * 64 + jn * 8 + t * 2;
            float2 r0 = make_float2(acc[im][jn][0] + bs0, acc[im][jn][1] + bs0);
            float2 r1 = make_float2(acc[im][jn][2] + bs1, acc[im][jn][3] + bs1);
            *(float2*)&Y[(size_t)row * HW + col] = r0;
            *(float2*)&Y[(size_t)(row + 8) * HW + col] = r1;
        }
    }
}

// ---------------------------------------------------------------------------
// K2 v3: depthwise 3x3 (4 pixels/thread, 32x32 tile) + window l2norm (q,k)
// + bf16 pair packing, writing K3-ready layouts.
// A thread's 4 rows sit in ONE half-window; partner half comes from warp ty^1
// via a tiny smem exchange.
// ---------------------------------------------------------------------------
__global__ __launch_bounds__(256) void k_dwconv(
    const float* __restrict__ in, const float* __restrict__ wd,
    uint32_t* __restrict__ gq, uint32_t* __restrict__ gk,
    uint32_t* __restrict__ gvh, uint32_t* __restrict__ gvl)
{
    const int plane = blockIdx.z;
    const int b = plane / C3, ch3 = plane - b * C3;
    const int x0 = blockIdx.x * 32, y0 = blockIdx.y * 32;

    __shared__ float sm[34][36];
    __shared__ float red[8][4];

    const float* P = in + (size_t)plane * HW;
    const int tx = threadIdx.x, ty = threadIdx.y;
    const int lt = ty * 32 + tx;

    for (int e = lt; e < 34 * 36; e += 256) {
        int r = e / 36, cc = e - r * 36;
        int gy = y0 - 1 + r, gx = x0 - 1 + cc;
        float v = 0.f;
        if (gy >= 0 && gy < IMG && gx >= 0 && gx < IMG) v = P[gy * IMG + gx];
        sm[r][cc] = v;
    }
    __syncthreads();

    const float* wp = wd + ch3 * 9;
    float w[9];
#pragma unroll
    for (int i = 0; i < 9; i++) w[i] = __ldg(wp + i);

    float a[6][3];
#pragma unroll
    for (int r = 0; r < 6; r++)
#pragma unroll
        for (int c2 = 0; c2 < 3; c2++)
            a[r][c2] = sm[ty * 4 + r][tx + c2];

    float s[4];
#pragma unroll
    for (int j = 0; j < 4; j++) {
        s[j] = w[0] * a[j][0] + w[1] * a[j][1] + w[2] * a[j][2]
             + w[3] * a[j + 1][0] + w[4] * a[j + 1][1] + w[5] * a[j + 1][2]
             + w[6] * a[j + 2][0] + w[7] * a[j + 2][1] + w[8] * a[j + 2][2];
    }

    const int z = ch3 / 192;
    const int head = (ch3 % 192) >> 5;
    const int c = ch3 & 31;
    const int yl0 = ty * 4;
    const int win = b * 1024 + ((y0 + yl0) >> 3) * 32 + (x0 >> 3) + (tx >> 3);
    const int ywin = yl0 & 7;        // 0 or 4
    const size_t dst0 = (((size_t)win * HEADS + head) * CH + c) * NPAIR
                        + ywin * 4 + ((tx & 7) >> 1);

    if (z < 2) {
        // window l2 norm: 8-lane (col) reduce + partner half-window from ty^1
        float ss = s[0] * s[0] + s[1] * s[1] + s[2] * s[2] + s[3] * s[3];
        ss += __shfl_xor_sync(0xffffffffu, ss, 1);
        ss += __shfl_xor_sync(0xffffffffu, ss, 2);
        ss += __shfl_xor_sync(0xffffffffu, ss, 4);
        if ((tx & 7) == 0) red[ty][tx >> 3] = ss;
        __syncthreads();
        float tot = ss + red[ty ^ 1][tx >> 3];
        float inv = 1.0f / fmaxf(sqrtf(tot), 1e-12f);
        uint32_t* dst = (z == 0) ? gq : gk;
#pragma unroll
        for (int j = 0; j < 4; j++) {
            float sn = s[j] * inv;
            float so = __shfl_down_sync(0xffffffffu, sn, 1);
            if (!(tx & 1)) dst[dst0 + 4 * j] = pack_hi(sn, so);
        }
    } else {
#pragma unroll
        for (int j = 0; j < 4; j++) {
            float so = __shfl_down_sync(0xffffffffu, s[j], 1);
            if (!(tx & 1)) {
                uint32_t hp, lp;
                split2(s[j], so, hp, lp);
                gvh[dst0 + 4 * j] = hp;
                gvl[dst0 + 4 * j] = lp;
            }
        }
    }
}

// ---------------------------------------------------------------------------
// K3: one block per window, 8 warps, loops 6 heads. q/k/v arrive pre-packed
// from K2; cross-head uint32 prefetch. (R11 structure over R10 body)
// ---------------------------------------------------------------------------
#define SMA_MWH 0
#define SMA_MWL 8448
#define SMA_QH 16896
#define SMA_KH 21120
#define SMA_VPH 25344
#define SMA_VPL 29568
#define SMA_VTH 33792
#define SMA_VTL 38144
#define SMA_VS  42496
#define SMA_AS  42496
#define SMA_AH  51200
#define SMA_AL  53376
#define SMA_MBS 55552
#define SMA_TOTAL 55808

__global__ __launch_bounds__(256, 2) void k_attn(
    const uint32_t* __restrict__ gq, const uint32_t* __restrict__ gk,
    const uint32_t* __restrict__ gvh, const uint32_t* __restrict__ gvl,
    const float* __restrict__ temperature,
    const float* __restrict__ mlp_w, const float* __restrict__ mlp_b,
    float* __restrict__ out)
{
    extern __shared__ char smraw[];
    uint32_t* mwh = (uint32_t*)(smraw + SMA_MWH);
    uint32_t* mwl = (uint32_t*)(smraw + SMA_MWL);
    uint32_t* qh  = (uint32_t*)(smraw + SMA_QH);
    uint32_t* kh  = (uint32_t*)(smraw + SMA_KH);
    uint32_t* vph = (uint32_t*)(smraw + SMA_VPH);
    uint32_t* vpl = (uint32_t*)(smraw + SMA_VPL);
    uint32_t* vth = (uint32_t*)(smraw + SMA_VTH);
    uint32_t* vtl = (uint32_t*)(smraw + SMA_VTL);
    float*    vsf = (float*)(smraw + SMA_VS);
    float*    As  = (float*)(smraw + SMA_AS);
    uint32_t* Ahs = (uint32_t*)(smraw + SMA_AH);
    uint32_t* Als = (uint32_t*)(smraw + SMA_AL);
    float*    mbs = (float*)(smraw + SMA_MBS);

    const int winId = blockIdx.x;
    const int tid = threadIdx.x;
    const int lane = tid & 31;
    const int wid = tid >> 5;
    const int g = lane >> 2;
    const int t = lane & 3;
    const int mi = wid >> 2;
    const int ni = wid & 3;

    // mlp_w pack (once per block)
    {
        int y = tid >> 2, pp0 = (tid & 3) * 8;
        const float* p = mlp_w + y * 64 + pp0 * 2;
        float4 f0 = *(const float4*)p;
        float4 f1 = *(const float4*)(p + 4);
        float4 f2 = *(const float4*)(p + 8);
        float4 f3 = *(const float4*)(p + 12);
        float f[16] = {f0.x, f0.y, f0.z, f0.w, f1.x, f1.y, f1.z, f1.w,
                       f2.x, f2.y, f2.z, f2.w, f3.x, f3.y, f3.z, f3.w};
#pragma unroll
        for (int i = 0; i < 8; i++) {
            uint32_t hp, lp;
            split2(f[2 * i], f[2 * i + 1], hp, lp);
            mwh[y * 33 + pp0 + i] = hp;
            mwl[y * 33 + pp0 + i] = lp;
        }
    }
    if (tid < 64) mbs[tid] = mlp_b[tid];

    const int rr = tid >> 3;        // channel
    const int seg = tid & 7;        // 4-pair segment

    const int bb = winId >> 10, rem = winId & 1023;
    const int h1 = rem >> 5, w1 = rem & 31;

    uint32_t q4[4], k4[4], vh4[4], vl4[4];
    {
        const size_t hb = ((size_t)(winId * HEADS) * CH + rr) * NPAIR + seg * 4;
        *(uint4*)q4  = *(const uint4*)(gq + hb);
        *(uint4*)k4  = *(const uint4*)(gk + hb);
        *(uint4*)vh4 = *(const uint4*)(gvh + hb);
        *(uint4*)vl4 = *(const uint4*)(gvl + hb);
    }

    for (int head = 0; head < HEADS; head++) {
        __syncthreads();   // (a)

#pragma unroll
        for (int i = 0; i < 4; i++) {
            qh[rr * 33 + seg * 4 + i] = q4[i];
            kh[rr * 33 + seg * 4 + i] = k4[i];
            vph[rr * 33 + seg * 4 + i] = vh4[i];
            vpl[rr * 33 + seg * 4 + i] = vl4[i];
        }
        {
            float e[8];
#pragma unroll
            for (int i = 0; i < 4; i++) {
                __nv_bfloat162 h2 = *reinterpret_cast<__nv_bfloat162*>(&vh4[i]);
                __nv_bfloat162 l2 = *reinterpret_cast<__nv_bfloat162*>(&vl4[i]);
                e[2 * i] = __bfloat162float(h2.x) + __bfloat162float(l2.x);
                e[2 * i + 1] = __bfloat162float(h2.y) + __bfloat162float(l2.y);
            }
            *(float4*)&vsf[rr * 68 + seg * 8] = make_float4(e[0], e[1], e[2], e[3]);
            *(float4*)&vsf[rr * 68 + seg * 8 + 4] = make_float4(e[4], e[5], e[6], e[7]);
        }
        if (head + 1 < HEADS) {
            const size_t hb = ((size_t)(winId * HEADS + head + 1) * CH + rr) * NPAIR + seg * 4;
            *(uint4*)q4  = *(const uint4*)(gq + hb);
            *(uint4*)k4  = *(const uint4*)(gk + hb);
            *(uint4*)vh4 = *(const uint4*)(gvh + hb);
            *(uint4*)vl4 = *(const uint4*)(gvl + hb);
        }
        __syncthreads();   // (b)

        {
            int x = tid >> 2;
            int dpb = tid & 3;
#pragma unroll
            for (int i = 0; i < 4; i++) {
                int dp = dpb + 4 * i;
                float e0 = vsf[(2 * dp) * 68 + x];
                float e1 = vsf[(2 * dp + 1) * 68 + x];
                uint32_t hp, lp;
                split2(e0, e1, hp, lp);
                vth[x * 17 + dp] = hp;
                vtl[x * 17 + dp] = lp;
            }
        }
        __syncthreads();   // (c)

        {
            float cacc[4] = {0.f, 0.f, 0.f, 0.f};
#pragma unroll
            for (int c = 0; c < 4; c++) {
                int p0 = c * 8 + t, p1 = p0 + 4;
                uint32_t A[4];
                A[0] = qh[(mi * 16 + g) * 33 + p0];
                A[1] = qh[(mi * 16 + g + 8) * 33 + p0];
                A[2] = qh[(mi * 16 + g) * 33 + p1];
                A[3] = qh[(mi * 16 + g + 8) * 33 + p1];
                uint32_t b0 = kh[(ni * 8 + g) * 33 + p0];
                uint32_t b1 = kh[(ni * 8 + g) * 33 + p1];
                mma16816(cacc, A, b0, b1);
            }
            const float temp = temperature[head];
            As[(mi * 16 + g) * 36 + ni * 8 + 2 * t] = cacc[0] * temp;
            As[(mi * 16 + g) * 36 + ni * 8 + 2 * t + 1] = cacc[1] * temp;
            As[(mi * 16 + g + 8) * 36 + ni * 8 + 2 * t] = cacc[2] * temp;
            As[(mi * 16 + g + 8) * 36 + ni * 8 + 2 * t + 1] = cacc[3] * temp;
        }
        __syncthreads();   // (d)

        {
            int r = tid >> 3, j0 = (tid & 7) * 4;
            float4 v4 = *(const float4*)&As[r * 36 + j0];
            float v[4] = {v4.x, v4.y, v4.z, v4.w};
            float m = fmaxf(fmaxf(v[0], v[1]), fmaxf(v[2], v[3]));
            m = fmaxf(m, __shfl_xor_sync(0xffffffffu, m, 1));
            m = fmaxf(m, __shfl_xor_sync(0xffffffffu, m, 2));
            m = fmaxf(m, __shfl_xor_sync(0xffffffffu, m, 4));
            float s = 0.f;
#pragma unroll
            for (int i = 0; i < 4; i++) { v[i] = __expf(v[i] - m); s += v[i]; }
            s += __shfl_xor_sync(0xffffffffu, s, 1);
            s += __shfl_xor_sync(0xffffffffu, s, 2);
            s += __shfl_xor_sync(0xffffffffu, s, 4);
            float inv = 1.0f / s;
            int jp = (tid & 7) * 2;
            uint32_t hp, lp;
            split2(v[0] * inv, v[1] * inv, hp, lp);
            Ahs[r * 17 + jp] = hp; Als[r * 17 + jp] = lp;
            split2(v[2] * inv, v[3] * inv, hp, lp);
            Ahs[r * 17 + jp + 1] = hp; Als[r * 17 + jp + 1] = lp;
        }
        __syncthreads();   // (e)

        {
            float oa[2][4], ga[2][4];
#pragma unroll
            for (int nt = 0; nt < 2; nt++)
#pragma unroll
                for (int r = 0; r < 4; r++) { oa[nt][r] = 0.f; ga[nt][r] = 0.f; }

#pragma unroll
            for (int c = 0; c < 2; c++) {
                int p0 = c * 8 + t, p1 = p0 + 4;
                uint32_t Ahf[4], Alf[4];
                Ahf[0] = Ahs[(mi * 16 + g) * 17 + p0];
                Ahf[1] = Ahs[(mi * 16 + g + 8) * 17 + p0];
                Ahf[2] = Ahs[(mi * 16 + g) * 17 + p1];
                Ahf[3] = Ahs[(mi * 16 + g + 8) * 17 + p1];
                Alf[0] = Als[(mi * 16 + g) * 17 + p0];
                Alf[1] = Als[(mi * 16 + g + 8) * 17 + p0];
                Alf[2] = Als[(mi * 16 + g) * 17 + p1];
                Alf[3] = Als[(mi * 16 + g + 8) * 17 + p1];
#pragma unroll
                for (int nt = 0; nt < 2; nt++) {
                    int n = (ni * 2 + nt) * 8 + g;
                    uint32_t bh0 = vth[n * 17 + p0], bh1 = vth[n * 17 + p1];
                    uint32_t bl0 = vtl[n * 17 + p0], bl1 = vtl[n * 17 + p1];
                    mma16816(oa[nt], Ahf, bl0, bl1);
                    mma16816(oa[nt], Alf, bh0, bh1);
                    mma16816(oa[nt], Ahf, bh0, bh1);
                }
            }
#pragma unroll
            for (int c = 0; c < 4; c++) {
                int p0 = c * 8 + t, p1 = p0 + 4;
                uint32_t Vh[4], Vl[4];
                Vh[0] = vph[(mi * 16 + g) * 33 + p0];
                Vh[1] = vph[(mi * 16 + g + 8) * 33 + p0];
                Vh[2] = vph[(mi * 16 + g) * 33 + p1];
                Vh[3] = vph[(mi * 16 + g + 8) * 33 + p1];
                Vl[0] = vpl[(mi * 16 + g) * 33 + p0];
                Vl[1] = vpl[(mi * 16 + g + 8) * 33 + p0];
                Vl[2] = vpl[(mi * 16 + g) * 33 + p1];
                Vl[3] = vpl[(mi * 16 + g + 8) * 33 + p1];
#pragma unroll
                for (int nt = 0; nt < 2; nt++) {
                    int n = (ni * 2 + nt) * 8 + g;
                    uint32_t bh0 = mwh[n * 33 + p0], bh1 = mwh[n * 33 + p1];
                    uint32_t bl0 = mwl[n * 33 + p0], bl1 = mwl[n * 33 + p1];
                    mma16816(ga[nt], Vh, bl0, bl1);
                    mma16816(ga[nt], Vl, bh0, bh1);
                    mma16816(ga[nt], Vh, bh0, bh1);
                }
            }
#pragma unroll
            for (int nt = 0; nt < 2; nt++) {
                int ntok = ni * 2 + nt;
                float b0 = mbs[ntok * 8 + 2 * t];
                float b1 = mbs[ntok * 8 + 2 * t + 1];
#pragma unroll
                for (int half = 0; half < 2; half++) {
                    int row = mi * 16 + g + half * 8;
                    float o0 = oa[nt][half * 2], o1 = oa[nt][half * 2 + 1];
                    float x0 = ga[nt][half * 2] + b0;
                    float x1 = ga[nt][half * 2 + 1] + b1;
                    float ge0 = 0.5f * x0 * (1.0f + erff(x0 * 0.70710678118654752f));
                    float ge1 = 0.5f * x1 * (1.0f + erff(x1 * 0.70710678118654752f));
                    size_t addr = ((((size_t)bb * C_IN + head * CH + row) * IMG
                                    + h1 * 8 + ntok) * IMG) + w1 * 8 + 2 * t;
                    *(float2*)&out[addr] = make_float2(o0 * ge0, o1 * ge1);
                }
            }
        }
    }
}

// ---------------------------------------------------------------------------
extern "C" void kernel_launch(void* const* d_in, const int* in_sizes, int n_in,
                              void* d_out, int out_size)
{
    const float* x           = (const float*)d_in[0];
    const float* w_qkv       = (const float*)d_in[1];
    const float* w_dw        = (const float*)d_in[2];
    const float* temperature = (const float*)d_in[3];
    const float* mlp_w       = (const float*)d_in[4];
    const float* mlp_b       = (const float*)d_in[5];
    const float* proj_w      = (const float*)d_in[6];
    const float* proj_b      = (const float*)d_in[7];
    float* out = (float*)d_out;

    float *qkv1, *att;
    uint32_t *gq, *gk, *gvh, *gvl;
    cudaGetSymbolAddress((void**)&qkv1, g_qkv1);
    cudaGetSymbolAddress((void**)&att, g_att);
    cudaGetSymbolAddress((void**)&gq, g_q);
    cudaGetSymbolAddress((void**)&gk, g_k);
    cudaGetSymbolAddress((void**)&gvh, g_vh);
    cudaGetSymbolAddress((void**)&gvl, g_vl);

    cudaFuncSetAttribute(k_attn, cudaFuncAttributeMaxDynamicSharedMemorySize, SMA_TOTAL);

    k_gemm_mma<<<dim3(HW / 256, C3 / 64, BATCH), 256>>>(w_qkv, x, qkv1, nullptr, C3);
    k_dwconv<<<dim3(IMG / 32, IMG / 32, BATCH * C3), dim3(32, 8)>>>(qkv1, w_dw, gq, gk, gvh, gvl);
    k_attn<<<NWIN, 256, SMA_TOTAL>>>(gq, gk, gvh, gvl, temperature, mlp_w, mlp_b, att);
    k_gemm_mma<<<dim3(HW / 256, C_IN / 64, BATCH), 256>>>(proj_w, att, out, proj_b, C_IN);
}

// round 16
// speedup vs baseline: 1.0211x; 1.0211x over previous
#include <cuda_runtime.h>
#include <cuda_bf16.h>
#include <math.h>
#include <stdint.h>

// ---------------- problem constants ----------------
#define BATCH 2
#define C_IN 192
#define C3 576
#define HW 65536
#define IMG 256
#define HEADS 6
#define CH 32
#define WS 8
#define NTOK 64
#define NWIN 2048

__device__ float g_qkv1[(size_t)BATCH * C3 * HW];
__device__ float g_win[(size_t)3 * NWIN * HEADS * CH * NTOK];
__device__ float g_att[(size_t)BATCH * C_IN * HW];

// ---------------------------------------------------------------------------
// bf16 helpers (pair-packed b32: low 16 = even-k, high 16 = odd-k)
// ---------------------------------------------------------------------------
__device__ __forceinline__ void split2(float e0, float e1, uint32_t& hp, uint32_t& lp)
{
    __nv_bfloat16 h0 = __float2bfloat16(e0);
    __nv_bfloat16 h1 = __float2bfloat16(e1);
    __nv_bfloat16 l0 = __float2bfloat16(e0 - __bfloat162float(h0));
    __nv_bfloat16 l1 = __float2bfloat16(e1 - __bfloat162float(h1));
    __nv_bfloat162 hh; hh.x = h0; hh.y = h1;
    __nv_bfloat162 ll; ll.x = l0; ll.y = l1;
    hp = *reinterpret_cast<uint32_t*>(&hh);
    lp = *reinterpret_cast<uint32_t*>(&ll);
}

__device__ __forceinline__ uint32_t pack_hi(float e0, float e1)
{
    __nv_bfloat162 hh; hh.x = __float2bfloat16(e0); hh.y = __float2bfloat16(e1);
    return *reinterpret_cast<uint32_t*>(&hh);
}

__device__ __forceinline__ void mma16816(float* d, const uint32_t* a, uint32_t b0, uint32_t b1)
{
    asm volatile(
        "mma.sync.aligned.m16n8k16.row.col.f32.bf16.bf16.f32 "
        "{%0,%1,%2,%3}, {%4,%5,%6,%7}, {%8,%9}, {%0,%1,%2,%3};"
        : "+f"(d[0]), "+f"(d[1]), "+f"(d[2]), "+f"(d[3])
        : "r"(a[0]), "r"(a[1]), "r"(a[2]), "r"(a[3]), "r"(b0), "r"(b1));
}

// ---------------------------------------------------------------------------
// K1/K4: GEMM (R10 tiling). CTA 64x256x32, 8 warps 2x4, warp tile 32x64,
// conflict-free X pack, launch_bounds(256,2).
// Precision split: q/k output tiles (K1, blockIdx.y<6, no bias) drop the
// Wh*Xl term -> 2 MMA passes and hi-only X pack. v tiles and all of K4
// (bias!=null) keep the full 3-pass split.
// ---------------------------------------------------------------------------
__global__ __launch_bounds__(256, 2) void k_gemm_mma(
    const float* __restrict__ Wt, const float* __restrict__ Xall,
    float* __restrict__ Yall, const float* __restrict__ bias, int M)
{
    const float* X = Xall + (size_t)blockIdx.z * C_IN * HW;
    float* Y = Yall + (size_t)blockIdx.z * (size_t)M * HW;
    const int oTile = blockIdx.y * 64;
    const int pTile = blockIdx.x * 256;
    const bool full = (bias != nullptr) || (blockIdx.y >= 6);

    __shared__ uint32_t WsH[2][64][9], WsL[2][64][9];
    __shared__ uint32_t XsH[2][256][9], XsL[2][256][9];

    const int tid = threadIdx.x;
    const int lane = tid & 31;
    const int wid = tid >> 5;
    const int warpM = wid >> 2;
    const int warpN = wid & 3;
    const int g = lane >> 2;
    const int t = lane & 3;

    float acc[2][8][4];
#pragma unroll
    for (int im = 0; im < 2; im++)
#pragma unroll
        for (int jn = 0; jn < 8; jn++)
#pragma unroll
            for (int r = 0; r < 4; r++) acc[im][jn][r] = 0.f;

    const int wo = tid >> 2;
    const int wsub = tid & 3;

    for (int k0 = 0; k0 < 192; k0 += 32) {
        {
            const float* wptr = &Wt[(size_t)(oTile + wo) * 192 + k0 + wsub * 8];
            float4 f0 = *(const float4*)wptr;
            float4 f1 = *(const float4*)(wptr + 4);
            float f[8] = {f0.x, f0.y, f0.z, f0.w, f1.x, f1.y, f1.z, f1.w};
#pragma unroll
            for (int j = 0; j < 4; j++) {
                uint32_t hp, lp;
                split2(f[2 * j], f[2 * j + 1], hp, lp);
                int kk2 = wsub * 4 + j;
                int ch = kk2 >> 3, cc = kk2 & 7;
                WsH[ch][wo][cc] = hp;
                WsL[ch][wo][cc] = lp;
            }
        }
        {
#pragma unroll
            for (int it = 0; it < 2; it++) {
                int kp = (tid >> 5) + it * 8;
                int ch = kp >> 3, cc = kp & 7;
                const float* r0 = X + (size_t)(k0 + 2 * kp) * HW + pTile + lane;
#pragma unroll
                for (int pm = 0; pm < 8; pm++) {
                    float f0 = r0[pm * 32];
                    float f1 = r0[pm * 32 + HW];
                    if (full) {
                        uint32_t hp, lp;
                        split2(f0, f1, hp, lp);
                        XsH[ch][lane + 32 * pm][cc] = hp;
                        XsL[ch][lane + 32 * pm][cc] = lp;
                    } else {
                        XsH[ch][lane + 32 * pm][cc] = pack_hi(f0, f1);
                    }
                }
            }
        }
        __syncthreads();

#pragma unroll
        for (int ch = 0; ch < 2; ch++) {
            uint32_t Ah[2][4], Al[2][4];
#pragma unroll
            for (int im = 0; im < 2; im++) {
                int r0 = warpM * 32 + im * 16 + g;
                Ah[im][0] = WsH[ch][r0][t];
                Ah[im][1] = WsH[ch][r0 + 8][t];
                Ah[im][2] = WsH[ch][r0][t + 4];
                Ah[im][3] = WsH[ch][r0 + 8][t + 4];
                Al[im][0] = WsL[ch][r0][t];
                Al[im][1] = WsL[ch][r0 + 8][t];
                Al[im][2] = WsL[ch][r0][t + 4];
                Al[im][3] = WsL[ch][r0 + 8][t + 4];
            }
#pragma unroll
            for (int jn = 0; jn < 8; jn++) {
                int col = warpN * 64 + jn * 8 + g;
                uint32_t bh0 = XsH[ch][col][t], bh1 = XsH[ch][col][t + 4];
#pragma unroll
                for (int im = 0; im < 2; im++)
                    mma16816(acc[im][jn], Al[im], bh0, bh1);
                if (full) {
                    uint32_t bl0 = XsL[ch][col][t], bl1 = XsL[ch][col][t + 4];
#pragma unroll
                    for (int im = 0; im < 2; im++)
                        mma16816(acc[im][jn], Ah[im], bl0, bl1);
                }
#pragma unroll
                for (int im = 0; im < 2; im++)
                    mma16816(acc[im][jn], Ah[im], bh0, bh1);
            }
        }
        __syncthreads();
    }

#pragma unroll
    for (int im = 0; im < 2; im++) {
        int row = oTile + warpM * 32 + im * 16 + g;
        float bs0 = bias ? bias[row] : 0.f;
        float bs1 = bias ? bias[row + 8] : 0.f;
#pragma unroll
        for (int jn = 0; jn < 8; jn++) {
            int col = pTile + warpN * 64 + jn * 8 + t * 2;
            float2 r0 = make_float2(acc[im][jn][0] + bs0, acc[im][jn][1] + bs0);
            float2 r1 = make_float2(acc[im][jn][2] + bs1, acc[im][jn][3] + bs1);
            *(float2*)&Y[(size_t)row * HW + col] = r0;
            *(float2*)&Y[(size_t)(row + 8) * HW + col] = r1;
        }
    }
}

// ---------------------------------------------------------------------------
// K2 v3: depthwise 3x3 + window scatter, 8 adjacent pixels per thread.
// Block 32x8 threads handles a 32x64 tile; each thread's 8 rows span exactly
// one window column -> win/tok math computed once, dst = dst0 + 8j.
// ---------------------------------------------------------------------------
__global__ __launch_bounds__(256) void k_dwconv(
    const float* __restrict__ in, const float* __restrict__ wd,
    float* __restrict__ outWin)
{
    const int plane = blockIdx.z;
    const int b = plane / C3, ch3 = plane - b * C3;
    const int x0 = blockIdx.x * 32, y0 = blockIdx.y * 64;

    __shared__ float sm[66][36];
    const float* P = in + (size_t)plane * HW;
    const int tx = threadIdx.x, ty = threadIdx.y;
    const int lt = ty * 32 + tx;

    for (int e = lt; e < 66 * 36; e += 256) {
        int r = e / 36, cc = e - r * 36;
        int gy = y0 - 1 + r, gx = x0 - 1 + cc;
        float v = 0.f;
        if (gy >= 0 && gy < IMG && gx >= 0 && gx < IMG) v = P[gy * IMG + gx];
        sm[r][cc] = v;
    }
    __syncthreads();

    const float* wp = wd + ch3 * 9;
    float w[9];
#pragma unroll
    for (int i = 0; i < 9; i++) w[i] = __ldg(wp + i);

    float a[10][3];
#pragma unroll
    for (int r = 0; r < 10; r++)
#pragma unroll
        for (int c2 = 0; c2 < 3; c2++)
            a[r][c2] = sm[ty * 8 + r][tx + c2];

    const int z = ch3 / 192;
    const int head = (ch3 % 192) >> 5;
    const int c = ch3 & 31;
    const int win = b * 1024 + ((y0 >> 3) + ty) * 32 + (x0 >> 3) + (tx >> 3);
    size_t dst0 = ((((size_t)z * NWIN + win) * HEADS + head) * CH + c) * NTOK + (tx & 7);

#pragma unroll
    for (int j = 0; j < 8; j++) {
        float s = w[0] * a[j][0] + w[1] * a[j][1] + w[2] * a[j][2]
                + w[3] * a[j + 1][0] + w[4] * a[j + 1][1] + w[5] * a[j + 1][2]
                + w[6] * a[j + 2][0] + w[7] * a[j + 2][1] + w[8] * a[j + 2][2];
        outWin[dst0 + 8 * j] = s;
    }
}

// ---------------------------------------------------------------------------
// K3 (register MMA): one block per window, 8 warps, loops 6 heads,
// cross-head register prefetch. (R10/R14, proven)
// ---------------------------------------------------------------------------
#define SMA_MWH 0
#define SMA_MWL 8448
#define SMA_QH 16896
#define SMA_KH 21120
#define SMA_VPH 25344
#define SMA_VPL 29568
#define SMA_VTH 33792
#define SMA_VTL 38144
#define SMA_VS  42496
#define SMA_AS  42496
#define SMA_AH  51200
#define SMA_AL  53376
#define SMA_MBS 55552
#define SMA_TOTAL 55808

__global__ __launch_bounds__(256) void k_attn(
    const float* __restrict__ winBuf, const float* __restrict__ temperature,
    const float* __restrict__ mlp_w, const float* __restrict__ mlp_b,
    float* __restrict__ out)
{
    extern __shared__ char smraw[];
    uint32_t* mwh = (uint32_t*)(smraw + SMA_MWH);
    uint32_t* mwl = (uint32_t*)(smraw + SMA_MWL);
    uint32_t* qh  = (uint32_t*)(smraw + SMA_QH);
    uint32_t* kh  = (uint32_t*)(smraw + SMA_KH);
    uint32_t* vph = (uint32_t*)(smraw + SMA_VPH);
    uint32_t* vpl = (uint32_t*)(smraw + SMA_VPL);
    uint32_t* vth = (uint32_t*)(smraw + SMA_VTH);
    uint32_t* vtl = (uint32_t*)(smraw + SMA_VTL);
    float*    vsf = (float*)(smraw + SMA_VS);
    float*    As  = (float*)(smraw + SMA_AS);
    uint32_t* Ahs = (uint32_t*)(smraw + SMA_AH);
    uint32_t* Als = (uint32_t*)(smraw + SMA_AL);
    float*    mbs = (float*)(smraw + SMA_MBS);

    const int winId = blockIdx.x;
    const int tid = threadIdx.x;
    const int lane = tid & 31;
    const int wid = tid >> 5;
    const int g = lane >> 2;
    const int t = lane & 3;
    const int mi = wid >> 2;
    const int ni = wid & 3;

    const size_t zs = (size_t)NWIN * HEADS * CH * NTOK;

    {
        int y = tid >> 2, pp0 = (tid & 3) * 8;
        const float* p = mlp_w + y * 64 + pp0 * 2;
        float4 f0 = *(const float4*)p;
        float4 f1 = *(const float4*)(p + 4);
        float4 f2 = *(const float4*)(p + 8);
        float4 f3 = *(const float4*)(p + 12);
        float f[16] = {f0.x, f0.y, f0.z, f0.w, f1.x, f1.y, f1.z, f1.w,
                       f2.x, f2.y, f2.z, f2.w, f3.x, f3.y, f3.z, f3.w};
#pragma unroll
        for (int i = 0; i < 8; i++) {
            uint32_t hp, lp;
            split2(f[2 * i], f[2 * i + 1], hp, lp);
            mwh[y * 33 + pp0 + i] = hp;
            mwl[y * 33 + pp0 + i] = lp;
        }
    }
    if (tid < 64) mbs[tid] = mlp_b[tid];

    const int rr = tid >> 3;
    const int seg = tid & 7;

    const int bb = winId >> 10, rem = winId & 1023;
    const int h1 = rem >> 5, w1 = rem & 31;

    float fq[8], fk[8], fv[8];
    {
        const size_t base0 = (size_t)(winId * HEADS) * (CH * NTOK);
        const float* pq = winBuf + base0 + rr * 64 + seg * 8;
        float4 a = *(const float4*)pq;
        float4 b = *(const float4*)(pq + 4);
        fq[0]=a.x; fq[1]=a.y; fq[2]=a.z; fq[3]=a.w; fq[4]=b.x; fq[5]=b.y; fq[6]=b.z; fq[7]=b.w;
        const float* pk = winBuf + zs + base0 + rr * 64 + seg * 8;
        a = *(const float4*)pk; b = *(const float4*)(pk + 4);
        fk[0]=a.x; fk[1]=a.y; fk[2]=a.z; fk[3]=a.w; fk[4]=b.x; fk[5]=b.y; fk[6]=b.z; fk[7]=b.w;
        const float* pv = winBuf + 2 * zs + base0 + rr * 64 + seg * 8;
        a = *(const float4*)pv; b = *(const float4*)(pv + 4);
        fv[0]=a.x; fv[1]=a.y; fv[2]=a.z; fv[3]=a.w; fv[4]=b.x; fv[5]=b.y; fv[6]=b.z; fv[7]=b.w;
    }

    for (int head = 0; head < HEADS; head++) {
        __syncthreads();

        {
            float ss = 0.f;
#pragma unroll
            for (int i = 0; i < 8; i++) ss += fq[i] * fq[i];
            ss += __shfl_xor_sync(0xffffffffu, ss, 1);
            ss += __shfl_xor_sync(0xffffffffu, ss, 2);
            ss += __shfl_xor_sync(0xffffffffu, ss, 4);
            float inv = 1.0f / fmaxf(sqrtf(ss), 1e-12f);
#pragma unroll
            for (int i = 0; i < 4; i++)
                qh[rr * 33 + seg * 4 + i] = pack_hi(fq[2 * i] * inv, fq[2 * i + 1] * inv);
        }
        {
            float ss = 0.f;
#pragma unroll
            for (int i = 0; i < 8; i++) ss += fk[i] * fk[i];
            ss += __shfl_xor_sync(0xffffffffu, ss, 1);
            ss += __shfl_xor_sync(0xffffffffu, ss, 2);
            ss += __shfl_xor_sync(0xffffffffu, ss, 4);
            float inv = 1.0f / fmaxf(sqrtf(ss), 1e-12f);
#pragma unroll
            for (int i = 0; i < 4; i++)
                kh[rr * 33 + seg * 4 + i] = pack_hi(fk[2 * i] * inv, fk[2 * i + 1] * inv);
        }
        {
#pragma unroll
            for (int i = 0; i < 4; i++) {
                uint32_t hp, lp;
                split2(fv[2 * i], fv[2 * i + 1], hp, lp);
                vph[rr * 33 + seg * 4 + i] = hp;
                vpl[rr * 33 + seg * 4 + i] = lp;
            }
            *(float4*)&vsf[rr * 68 + seg * 8] = make_float4(fv[0], fv[1], fv[2], fv[3]);
            *(float4*)&vsf[rr * 68 + seg * 8 + 4] = make_float4(fv[4], fv[5], fv[6], fv[7]);
        }
        if (head + 1 < HEADS) {
            const size_t basen = (size_t)(winId * HEADS + head + 1) * (CH * NTOK);
            const float* pq = winBuf + basen + rr * 64 + seg * 8;
            float4 a = *(const float4*)pq;
            float4 b = *(const float4*)(pq + 4);
            fq[0]=a.x; fq[1]=a.y; fq[2]=a.z; fq[3]=a.w; fq[4]=b.x; fq[5]=b.y; fq[6]=b.z; fq[7]=b.w;
            const float* pk = winBuf + zs + basen + rr * 64 + seg * 8;
            a = *(const float4*)pk; b = *(const float4*)(pk + 4);
            fk[0]=a.x; fk[1]=a.y; fk[2]=a.z; fk[3]=a.w; fk[4]=b.x; fk[5]=b.y; fk[6]=b.z; fk[7]=b.w;
            const float* pv = winBuf + 2 * zs + basen + rr * 64 + seg * 8;
            a = *(const float4*)pv; b = *(const float4*)(pv + 4);
            fv[0]=a.x; fv[1]=a.y; fv[2]=a.z; fv[3]=a.w; fv[4]=b.x; fv[5]=b.y; fv[6]=b.z; fv[7]=b.w;
        }
        __syncthreads();

        {
            int x = tid >> 2;
            int dpb = tid & 3;
#pragma unroll
            for (int i = 0; i < 4; i++) {
                int dp = dpb + 4 * i;
                float e0 = vsf[(2 * dp) * 68 + x];
                float e1 = vsf[(2 * dp + 1) * 68 + x];
                uint32_t hp, lp;
                split2(e0, e1, hp, lp);
                vth[x * 17 + dp] = hp;
                vtl[x * 17 + dp] = lp;
            }
        }
        __syncthreads();

        {
            float cacc[4] = {0.f, 0.f, 0.f, 0.f};
#pragma unroll
            for (int c = 0; c < 4; c++) {
                int p0 = c * 8 + t, p1 = p0 + 4;
                uint32_t A[4];
                A[0] = qh[(mi * 16 + g) * 33 + p0];
                A[1] = qh[(mi * 16 + g + 8) * 33 + p0];
                A[2] = qh[(mi * 16 + g) * 33 + p1];
                A[3] = qh[(mi * 16 + g + 8) * 33 + p1];
                uint32_t b0 = kh[(ni * 8 + g) * 33 + p0];
                uint32_t b1 = kh[(ni * 8 + g) * 33 + p1];
                mma16816(cacc, A, b0, b1);
            }
            const float temp = temperature[head];
            As[(mi * 16 + g) * 36 + ni * 8 + 2 * t] = cacc[0] * temp;
            As[(mi * 16 + g) * 36 + ni * 8 + 2 * t + 1] = cacc[1] * temp;
            As[(mi * 16 + g + 8) * 36 + ni * 8 + 2 * t] = cacc[2] * temp;
            As[(mi * 16 + g + 8) * 36 + ni * 8 + 2 * t + 1] = cacc[3] * temp;
        }
        __syncthreads();

        {
            int r = tid >> 3, j0 = (tid & 7) * 4;
            float4 v4 = *(const float4*)&As[r * 36 + j0];
            float v[4] = {v4.x, v4.y, v4.z, v4.w};
            float m = fmaxf(fmaxf(v[0], v[1]), fmaxf(v[2], v[3]));
            m = fmaxf(m, __shfl_xor_sync(0xffffffffu, m, 1));
            m = fmaxf(m, __shfl_xor_sync(0xffffffffu, m, 2));
            m = fmaxf(m, __shfl_xor_sync(0xffffffffu, m, 4));
            float s = 0.f;
#pragma unroll
            for (int i = 0; i < 4; i++) { v[i] = __expf(v[i] - m); s += v[i]; }
            s += __shfl_xor_sync(0xffffffffu, s, 1);
            s += __shfl_xor_sync(0xffffffffu, s, 2);
            s += __shfl_xor_sync(0xffffffffu, s, 4);
            float inv = 1.0f / s;
            int jp = (tid & 7) * 2;
            uint32_t hp, lp;
            split2(v[0] * inv, v[1] * inv, hp, lp);
            Ahs[r * 17 + jp] = hp; Als[r * 17 + jp] = lp;
            split2(v[2] * inv, v[3] * inv, hp, lp);
            Ahs[r * 17 + jp + 1] = hp; Als[r * 17 + jp + 1] = lp;
        }
        __syncthreads();

        {
            float oa[2][4], ga[2][4];
#pragma unroll
            for (int nt = 0; nt < 2; nt++)
#pragma unroll
                for (int r = 0; r < 4; r++) { oa[nt][r] = 0.f; ga[nt][r] = 0.f; }

#pragma unroll
            for (int c = 0; c < 2; c++) {
                int p0 = c * 8 + t, p1 = p0 + 4;
                uint32_t Ahf[4], Alf[4];
                Ahf[0] = Ahs[(mi * 16 + g) * 17 + p0];
                Ahf[1] = Ahs[(mi * 16 + g + 8) * 17 + p0];
                Ahf[2] = Ahs[(mi * 16 + g) * 17 + p1];
                Ahf[3] = Ahs[(mi * 16 + g + 8) * 17 + p1];
                Alf[0] = Als[(mi * 16 + g) * 17 + p0];
                Alf[1] = Als[(mi * 16 + g + 8) * 17 + p0];
                Alf[2] = Als[(mi * 16 + g) * 17 + p1];
                Alf[3] = Als[(mi * 16 + g + 8) * 17 + p1];
#pragma unroll
                for (int nt = 0; nt < 2; nt++) {
                    int n = (ni * 2 + nt) * 8 + g;
                    uint32_t bh0 = vth[n * 17 + p0], bh1 = vth[n * 17 + p1];
                    uint32_t bl0 = vtl[n * 17 + p0], bl1 = vtl[n * 17 + p1];
                    mma16816(oa[nt], Ahf, bl0, bl1);
                    mma16816(oa[nt], Alf, bh0, bh1);
                    mma16816(oa[nt], Ahf, bh0, bh1);
                }
            }
#pragma unroll
            for (int c = 0; c < 4; c++) {
                int p0 = c * 8 + t, p1 = p0 + 4;
                uint32_t Vh[4], Vl[4];
                Vh[0] = vph[(mi * 16 + g) * 33 + p0];
                Vh[1] = vph[(mi * 16 + g + 8) * 33 + p0];
                Vh[2] = vph[(mi * 16 + g) * 33 + p1];
                Vh[3] = vph[(mi * 16 + g + 8) * 33 + p1];
                Vl[0] = vpl[(mi * 16 + g) * 33 + p0];
                Vl[1] = vpl[(mi * 16 + g + 8) * 33 + p0];
                Vl[2] = vpl[(mi * 16 + g) * 33 + p1];
                Vl[3] = vpl[(mi * 16 + g + 8) * 33 + p1];
#pragma unroll
                for (int nt = 0; nt < 2; nt++) {
                    int n = (ni * 2 + nt) * 8 + g;
                    uint32_t bh0 = mwh[n * 33 + p0], bh1 = mwh[n * 33 + p1];
                    uint32_t bl0 = mwl[n * 33 + p0], bl1 = mwl[n * 33 + p1];
                    mma16816(ga[nt], Vh, bl0, bl1);
                    mma16816(ga[nt], Vl, bh0, bh1);
                    mma16816(ga[nt], Vh, bh0, bh1);
                }
            }
#pragma unroll
            for (int nt = 0; nt < 2; nt++) {
                int ntok = ni * 2 + nt;
                float b0 = mbs[ntok * 8 + 2 * t];
                float b1 = mbs[ntok * 8 + 2 * t + 1];
#pragma unroll
                for (int half = 0; half < 2; half++) {
                    int row = mi * 16 + g + half * 8;
                    float o0 = oa[nt][half * 2], o1 = oa[nt][half * 2 + 1];
                    float x0 = ga[nt][half * 2] + b0;
                    float x1 = ga[nt][half * 2 + 1] + b1;
                    float ge0 = 0.5f * x0 * (1.0f + erff(x0 * 0.70710678118654752f));
                    float ge1 = 0.5f * x1 * (1.0f + erff(x1 * 0.70710678118654752f));
                    size_t addr = ((((size_t)bb * C_IN + head * CH + row) * IMG
                                    + h1 * 8 + ntok) * IMG) + w1 * 8 + 2 * t;
                    *(float2*)&out[addr] = make_float2(o0 * ge0, o1 * ge1);
                }
            }
        }
    }
}

// ---------------------------------------------------------------------------
extern "C" void kernel_launch(void* const* d_in, const int* in_sizes, int n_in,
                              void* d_out, int out_size)
{
    const float* x           = (const float*)d_in[0];
    const float* w_qkv       = (const float*)d_in[1];
    const float* w_dw        = (const float*)d_in[2];
    const float* temperature = (const float*)d_in[3];
    const float* mlp_w       = (const float*)d_in[4];
    const float* mlp_b       = (const float*)d_in[5];
    const float* proj_w      = (const float*)d_in[6];
    const float* proj_b      = (const float*)d_in[7];
    float* out = (float*)d_out;

    float *qkv1, *winb, *att;
    cudaGetSymbolAddress((void**)&qkv1, g_qkv1);
    cudaGetSymbolAddress((void**)&winb, g_win);
    cudaGetSymbolAddress((void**)&att, g_att);

    cudaFuncSetAttribute(k_attn, cudaFuncAttributeMaxDynamicSharedMemorySize, SMA_TOTAL);

    k_gemm_mma<<<dim3(HW / 256, C3 / 64, BATCH), 256>>>(w_qkv, x, qkv1, nullptr, C3);
    k_dwconv<<<dim3(IMG / 32, IMG / 64, BATCH * C3), dim3(32, 8)>>>(qkv1, w_dw, winb);
    k_attn<<<NWIN, 256, SMA_TOTAL>>>(winb, temperature, mlp_w, mlp_b, att);
    k_gemm_mma<<<dim3(HW / 256, C_IN / 64, BATCH), 256>>>(proj_w, att, out, proj_b, C_IN);
}